// round 3
// baseline (speedup 1.0000x reference)
#include <cuda_runtime.h>
#include <math.h>
#include <stdint.h>

#define TB 16
#define TS 512
#define TE 1024
#define TH 16
#define TD 64

// Scratch (device globals: allocation-free rule)
static __device__ float  g_Q[(size_t)TB * TS * TE];
static __device__ float  g_K[(size_t)TB * TS * TE];
static __device__ double g_colpart[TB * TH * TS];
static __device__ double g_logits[TB * TS];

// ---------------------------------------------------------------------------
// GEMM: C[8192,1024] = tokens[8192,1024] * W[1024,1024]^T + bias
// blockIdx.z selects (Wq -> g_Q) or (Wk -> g_K). 128x128 tile, KC=16, 256 thr.
// ---------------------------------------------------------------------------
__global__ __launch_bounds__(256) void gemm_qk_kernel(
    const float* __restrict__ tokens,
    const float* __restrict__ Wq, const float* __restrict__ bq,
    const float* __restrict__ Wk, const float* __restrict__ bk)
{
    const float* W    = (blockIdx.z == 0) ? Wq : Wk;
    const float* bias = (blockIdx.z == 0) ? bq : bk;
    float*       C    = (blockIdx.z == 0) ? g_Q : g_K;

    __shared__ float As[16 * 128];   // As[k][m]
    __shared__ float Bs[16 * 128];   // Bs[k][n]

    const int t  = threadIdx.x;
    const int tx = t & 15, ty = t >> 4;
    const int m0 = blockIdx.y * 128;
    const int n0 = blockIdx.x * 128;
    const int lrow  = t & 127;
    const int lhalf = t >> 7;

    float acc[8][8];
#pragma unroll
    for (int i = 0; i < 8; i++)
#pragma unroll
        for (int j = 0; j < 8; j++) acc[i][j] = 0.f;

    const float* Arow = tokens + (size_t)(m0 + lrow) * TE;
    const float* Wrow = W      + (size_t)(n0 + lrow) * TE;

    for (int kk = 0; kk < TE; kk += 16) {
#pragma unroll
        for (int qq = 0; qq < 2; qq++) {
            int q = lhalf * 2 + qq;
            float4 va = *(const float4*)(Arow + kk + q * 4);
            As[(q*4+0)*128 + lrow] = va.x;
            As[(q*4+1)*128 + lrow] = va.y;
            As[(q*4+2)*128 + lrow] = va.z;
            As[(q*4+3)*128 + lrow] = va.w;
            float4 vb = *(const float4*)(Wrow + kk + q * 4);
            Bs[(q*4+0)*128 + lrow] = vb.x;
            Bs[(q*4+1)*128 + lrow] = vb.y;
            Bs[(q*4+2)*128 + lrow] = vb.z;
            Bs[(q*4+3)*128 + lrow] = vb.w;
        }
        __syncthreads();
#pragma unroll
        for (int k = 0; k < 16; k++) {
            float4 a0 = *(const float4*)&As[k*128 + ty*8];
            float4 a1 = *(const float4*)&As[k*128 + ty*8 + 4];
            float4 b0 = *(const float4*)&Bs[k*128 + tx*8];
            float4 b1 = *(const float4*)&Bs[k*128 + tx*8 + 4];
            float a[8]  = {a0.x, a0.y, a0.z, a0.w, a1.x, a1.y, a1.z, a1.w};
            float bb[8] = {b0.x, b0.y, b0.z, b0.w, b1.x, b1.y, b1.z, b1.w};
#pragma unroll
            for (int i = 0; i < 8; i++)
#pragma unroll
                for (int j = 0; j < 8; j++)
                    acc[i][j] = fmaf(a[i], bb[j], acc[i][j]);
        }
        __syncthreads();
    }

#pragma unroll
    for (int i = 0; i < 8; i++) {
        int m = m0 + ty * 8 + i;
#pragma unroll
        for (int j = 0; j < 8; j += 4) {
            int n = n0 + tx * 8 + j;
            float4 o;
            o.x = acc[i][j+0] + bias[n+0];
            o.y = acc[i][j+1] + bias[n+1];
            o.z = acc[i][j+2] + bias[n+2];
            o.w = acc[i][j+3] + bias[n+3];
            *(float4*)(C + (size_t)m * TE + n) = o;
        }
    }
}

// ---------------------------------------------------------------------------
// Fused attention-column kernel: one block per (b,h).
// For each 64-row q-tile: scores = Q Kh^T / 8 + 1, e = exp(score) kept in smem,
// fp64 row denominators, then col[s] += e[r][s]/denom[r] accumulated in fp64.
// ---------------------------------------------------------------------------
#define ATTN_SMEM ((64*512 + 64*64 + 64*128) * 4 + (512 + 64 + 64) * 8)

__global__ __launch_bounds__(256) void attn_col_kernel()
{
    extern __shared__ char smem_raw[];
    float*  Es     = (float*)smem_raw;            // [64][512] exp(scores)
    float*  Qs     = Es + 64 * 512;               // [64k][64r]
    float*  Ks     = Qs + 64 * 64;                // [64k][128s]
    double* colacc = (double*)(Ks + 64 * 128);    // [512]
    double* denom  = colacc + 512;                // [64]
    double* invd   = denom + 64;                  // [64]

    const int t  = threadIdx.x;
    const int tx = t & 15, ty = t >> 4;
    const int bh = blockIdx.x;
    const int b  = bh >> 4, h = bh & 15;

    colacc[t]       = 0.0;
    colacc[t + 256] = 0.0;

    const size_t base = ((size_t)b * TS) * TE + (size_t)h * TD;

    for (int qt = 0; qt < 8; qt++) {
        __syncthreads();   // protects Es/Qs/Ks reuse from previous iteration
        {
            int r  = t & 63;
            int qb = t >> 6;
            const float* qrow = g_Q + base + (size_t)(qt * 64 + r) * TE;
#pragma unroll
            for (int c = 0; c < 4; c++) {
                int q = qb * 4 + c;
                float4 v = *(const float4*)(qrow + q * 4);
                Qs[(q*4+0)*64 + r] = v.x;
                Qs[(q*4+1)*64 + r] = v.y;
                Qs[(q*4+2)*64 + r] = v.z;
                Qs[(q*4+3)*64 + r] = v.w;
            }
        }
        if (t < 64) denom[t] = 0.0;
        __syncthreads();

        for (int kt = 0; kt < 4; kt++) {
            {
                int s  = t & 127;
                int hv = t >> 7;
                const float* krow = g_K + base + (size_t)(kt * 128 + s) * TE;
#pragma unroll
                for (int c = 0; c < 8; c++) {
                    int q = hv * 8 + c;
                    float4 v = *(const float4*)(krow + q * 4);
                    Ks[(q*4+0)*128 + s] = v.x;
                    Ks[(q*4+1)*128 + s] = v.y;
                    Ks[(q*4+2)*128 + s] = v.z;
                    Ks[(q*4+3)*128 + s] = v.w;
                }
            }
            __syncthreads();

            float acc[4][8];
#pragma unroll
            for (int i = 0; i < 4; i++)
#pragma unroll
                for (int j = 0; j < 8; j++) acc[i][j] = 0.f;

#pragma unroll 8
            for (int k = 0; k < 64; k++) {
                float a0 = Qs[k*64 + ty*4 + 0];
                float a1 = Qs[k*64 + ty*4 + 1];
                float a2 = Qs[k*64 + ty*4 + 2];
                float a3 = Qs[k*64 + ty*4 + 3];
                float4 b0 = *(const float4*)&Ks[k*128 + tx*8];
                float4 b1 = *(const float4*)&Ks[k*128 + tx*8 + 4];
                float bb[8] = {b0.x, b0.y, b0.z, b0.w, b1.x, b1.y, b1.z, b1.w};
#pragma unroll
                for (int j = 0; j < 8; j++) {
                    acc[0][j] = fmaf(a0, bb[j], acc[0][j]);
                    acc[1][j] = fmaf(a1, bb[j], acc[1][j]);
                    acc[2][j] = fmaf(a2, bb[j], acc[2][j]);
                    acc[3][j] = fmaf(a3, bb[j], acc[3][j]);
                }
            }

#pragma unroll
            for (int i = 0; i < 4; i++) {
                float  e[8];
                double rs = 0.0;
#pragma unroll
                for (int j = 0; j < 8; j++) {
                    float sc = acc[i][j] * 0.125f + 1.0f;
                    e[j] = expf(sc);
                    rs += (double)e[j];
                }
                int row = ty * 4 + i;
                *(float4*)&Es[row*512 + kt*128 + tx*8]     = make_float4(e[0], e[1], e[2], e[3]);
                *(float4*)&Es[row*512 + kt*128 + tx*8 + 4] = make_float4(e[4], e[5], e[6], e[7]);
                atomicAdd(&denom[row], rs);
            }
            __syncthreads();
        }

        if (t < 64) invd[t] = 1.0 / denom[t];
        __syncthreads();

#pragma unroll
        for (int ss = 0; ss < 2; ss++) {
            int s = t + ss * 256;
            double a = colacc[s];
#pragma unroll 8
            for (int r = 0; r < 64; r++)
                a = fma((double)Es[r*512 + s], invd[r], a);
            colacc[s] = a;
        }
    }

    g_colpart[(size_t)bh * TS + t]       = colacc[t];
    g_colpart[(size_t)bh * TS + t + 256] = colacc[t + 256];
}

// ---------------------------------------------------------------------------
// col -> log_softmax logits (fp64, deterministic tree reductions)
// ---------------------------------------------------------------------------
__global__ __launch_bounds__(512) void logits_kernel()
{
    __shared__ double red[512];
    const int b = blockIdx.x;
    const int s = threadIdx.x;

    double v = 0.0;
#pragma unroll
    for (int h = 0; h < TH; h++)
        v += g_colpart[((size_t)b * TH + h) * TS + s];

    red[s] = v;
    __syncthreads();
    for (int off = 256; off > 0; off >>= 1) {
        if (s < off) { double o = red[s + off]; if (o > red[s]) red[s] = o; }
        __syncthreads();
    }
    double m = red[0];
    __syncthreads();
    red[s] = exp(v - m);
    __syncthreads();
    for (int off = 256; off > 0; off >>= 1) {
        if (s < off) red[s] += red[s + off];
        __syncthreads();
    }
    double lse = m + log(red[0]);
    g_logits[(size_t)b * TS + s] = v - lse;
}

// ---------------------------------------------------------------------------
// Threefry-2x32 (JAX-exact, PARTITIONABLE mode: default since jax 0.4.36)
//   counter = 64-bit flat index via iota_2x32_shape: x0 = hi32 = 0, x1 = lo32 = i
//   32-bit draw = bits1 ^ bits2  (the bit_width<=32 branch XORs the two words)
// Then Gumbel-argmax categorical + gather.
// ---------------------------------------------------------------------------
__device__ __forceinline__ void threefry2x32(
    unsigned k0, unsigned k1, unsigned x0, unsigned x1,
    unsigned& o0, unsigned& o1)
{
    const unsigned ks0 = k0, ks1 = k1, ks2 = k0 ^ k1 ^ 0x1BD11BDAu;
    x0 += ks0; x1 += ks1;
#define TF_RND(r) { x0 += x1; x1 = __funnelshift_l(x1, x1, r); x1 ^= x0; }
    TF_RND(13) TF_RND(15) TF_RND(26) TF_RND(6)   x0 += ks1; x1 += ks2 + 1u;
    TF_RND(17) TF_RND(29) TF_RND(16) TF_RND(24)  x0 += ks2; x1 += ks0 + 2u;
    TF_RND(13) TF_RND(15) TF_RND(26) TF_RND(6)   x0 += ks0; x1 += ks1 + 3u;
    TF_RND(17) TF_RND(29) TF_RND(16) TF_RND(24)  x0 += ks1; x1 += ks2 + 4u;
    TF_RND(13) TF_RND(15) TF_RND(26) TF_RND(6)   x0 += ks2; x1 += ks0 + 5u;
#undef TF_RND
    o0 = x0; o1 = x1;
}

__global__ __launch_bounds__(256) void sample_kernel(
    const float* __restrict__ tokens, float* __restrict__ out)
{
    const int warp = blockIdx.x * 8 + (threadIdx.x >> 5);   // 0..16383 = b*1024+j
    const int lane = threadIdx.x & 31;
    const int b = warp >> 10;
    const int j = warp & 1023;

    const double* lg = g_logits + (size_t)b * TS;

    double best = -1.0e300;
    int    bi   = 0;

    for (int s = lane; s < TS; s += 32) {
        unsigned i = (unsigned)warp * 512u + (unsigned)s;  // flat counter (< 2^23)
        unsigned o0, o1;
        threefry2x32(0u, 42u, 0u, i, o0, o1);              // (hi32=0, lo32=i)
        unsigned bits = o0 ^ o1;                           // partitionable 32-bit draw
        float f = __uint_as_float((bits >> 9) | 0x3f800000u) - 1.0f;
        float u = fmaxf(f, 1.17549435e-38f);          // jnp.finfo(f32).tiny
        double g = -log(-log((double)u));
        double v = g + lg[s];
        if (v > best) { best = v; bi = s; }           // first occurrence per lane
    }

#pragma unroll
    for (int off = 16; off > 0; off >>= 1) {
        double ov = __shfl_down_sync(0xffffffffu, best, off);
        int    oi = __shfl_down_sync(0xffffffffu, bi,   off);
        if (ov > best || (ov == best && oi < bi)) { best = ov; bi = oi; }
    }

    if (lane == 0)
        out[warp] = tokens[((size_t)b * TS + (size_t)bi) * TE + (size_t)j];
}

// ---------------------------------------------------------------------------
extern "C" void kernel_launch(void* const* d_in, const int* in_sizes, int n_in,
                              void* d_out, int out_size)
{
    (void)in_sizes; (void)n_in; (void)out_size;
    const float* tokens = (const float*)d_in[0];
    const float* Wq     = (const float*)d_in[1];
    const float* bq     = (const float*)d_in[2];
    const float* Wk     = (const float*)d_in[3];
    const float* bk     = (const float*)d_in[4];
    float* out = (float*)d_out;

    cudaFuncSetAttribute(attn_col_kernel,
                         cudaFuncAttributeMaxDynamicSharedMemorySize, ATTN_SMEM);

    gemm_qk_kernel<<<dim3(8, 64, 2), 256>>>(tokens, Wq, bq, Wk, bk);
    attn_col_kernel<<<256, 256, ATTN_SMEM>>>();
    logits_kernel<<<16, 512>>>();
    sample_kernel<<<2048, 256>>>(tokens, out);
}

// round 4
// speedup vs baseline: 1.0235x; 1.0235x over previous
#include <cuda_runtime.h>
#include <math.h>
#include <stdint.h>

#define TB 16
#define TS 512
#define TE 1024
#define TH 16
#define TD 64

// Scratch (device globals: allocation-free rule)
static __device__ float  g_Q[(size_t)TB * TS * TE];
static __device__ float  g_K[(size_t)TB * TS * TE];
static __device__ double g_colpart[TB * TH * TS];
static __device__ double g_logits[TB * TS];

// ---------------------------------------------------------------------------
// GEMM: C[8192,1024] = tokens[8192,1024] * W[1024,1024]^T + bias
// 128x128 tile, KC=16, 256 thr, register-prefetch pipeline, 2 blocks/SM.
// ---------------------------------------------------------------------------
__global__ __launch_bounds__(256, 2) void gemm_qk_kernel(
    const float* __restrict__ tokens,
    const float* __restrict__ Wq, const float* __restrict__ bq,
    const float* __restrict__ Wk, const float* __restrict__ bk)
{
    const float* W    = (blockIdx.z == 0) ? Wq : Wk;
    const float* bias = (blockIdx.z == 0) ? bq : bk;
    float*       C    = (blockIdx.z == 0) ? g_Q : g_K;

    __shared__ float As[16 * 128];   // As[k][m]
    __shared__ float Bs[16 * 128];   // Bs[k][n]

    const int t  = threadIdx.x;
    const int tx = t & 15, ty = t >> 4;
    const int m0 = blockIdx.y * 128;
    const int n0 = blockIdx.x * 128;
    const int lrow  = t & 127;
    const int lhalf = t >> 7;        // which 8-column half of the 16-k slab

    float acc[8][8];
#pragma unroll
    for (int i = 0; i < 8; i++)
#pragma unroll
        for (int j = 0; j < 8; j++) acc[i][j] = 0.f;

    const float* Arow = tokens + (size_t)(m0 + lrow) * TE + lhalf * 8;
    const float* Wrow = W      + (size_t)(n0 + lrow) * TE + lhalf * 8;

    // prefetch registers (next-stage global tile)
    float4 pa0, pa1, pb0, pb1;
    pa0 = *(const float4*)(Arow + 0);
    pa1 = *(const float4*)(Arow + 4);
    pb0 = *(const float4*)(Wrow + 0);
    pb1 = *(const float4*)(Wrow + 4);

    for (int kk = 0; kk < TE; kk += 16) {
        // scatter prefetched tile into transposed smem
        {
            int q0 = lhalf * 8;
            As[(q0+0)*128 + lrow] = pa0.x;
            As[(q0+1)*128 + lrow] = pa0.y;
            As[(q0+2)*128 + lrow] = pa0.z;
            As[(q0+3)*128 + lrow] = pa0.w;
            As[(q0+4)*128 + lrow] = pa1.x;
            As[(q0+5)*128 + lrow] = pa1.y;
            As[(q0+6)*128 + lrow] = pa1.z;
            As[(q0+7)*128 + lrow] = pa1.w;
            Bs[(q0+0)*128 + lrow] = pb0.x;
            Bs[(q0+1)*128 + lrow] = pb0.y;
            Bs[(q0+2)*128 + lrow] = pb0.z;
            Bs[(q0+3)*128 + lrow] = pb0.w;
            Bs[(q0+4)*128 + lrow] = pb1.x;
            Bs[(q0+5)*128 + lrow] = pb1.y;
            Bs[(q0+6)*128 + lrow] = pb1.z;
            Bs[(q0+7)*128 + lrow] = pb1.w;
        }
        __syncthreads();

        // issue next-stage LDG early; consumed only after next sync
        if (kk + 16 < TE) {
            pa0 = *(const float4*)(Arow + kk + 16);
            pa1 = *(const float4*)(Arow + kk + 20);
            pb0 = *(const float4*)(Wrow + kk + 16);
            pb1 = *(const float4*)(Wrow + kk + 20);
        }

#pragma unroll
        for (int k = 0; k < 16; k++) {
            float4 a0 = *(const float4*)&As[k*128 + ty*8];
            float4 a1 = *(const float4*)&As[k*128 + ty*8 + 4];
            float4 b0 = *(const float4*)&Bs[k*128 + tx*8];
            float4 b1 = *(const float4*)&Bs[k*128 + tx*8 + 4];
            float a[8]  = {a0.x, a0.y, a0.z, a0.w, a1.x, a1.y, a1.z, a1.w};
            float bb[8] = {b0.x, b0.y, b0.z, b0.w, b1.x, b1.y, b1.z, b1.w};
#pragma unroll
            for (int i = 0; i < 8; i++)
#pragma unroll
                for (int j = 0; j < 8; j++)
                    acc[i][j] = fmaf(a[i], bb[j], acc[i][j]);
        }
        __syncthreads();
    }

#pragma unroll
    for (int i = 0; i < 8; i++) {
        int m = m0 + ty * 8 + i;
#pragma unroll
        for (int j = 0; j < 8; j += 4) {
            int n = n0 + tx * 8 + j;
            float4 o;
            o.x = acc[i][j+0] + bias[n+0];
            o.y = acc[i][j+1] + bias[n+1];
            o.z = acc[i][j+2] + bias[n+2];
            o.w = acc[i][j+3] + bias[n+3];
            *(float4*)(C + (size_t)m * TE + n) = o;
        }
    }
}

// ---------------------------------------------------------------------------
// Fused attention-column kernel: one block per (b,h).
// Register-prefetched K tiles (next kt during current compute) and Q tiles
// (next qt during the colacc phase). Vectorized Qs loads.
// ---------------------------------------------------------------------------
#define ATTN_SMEM ((64*512 + 64*64 + 64*128) * 4 + (512 + 64 + 64) * 8)

__global__ __launch_bounds__(256) void attn_col_kernel()
{
    extern __shared__ char smem_raw[];
    float*  Es     = (float*)smem_raw;            // [64][512] exp(scores)
    float*  Qs     = Es + 64 * 512;               // [64k][64r]
    float*  Ks     = Qs + 64 * 64;                // [64k][128s]
    double* colacc = (double*)(Ks + 64 * 128);    // [512]
    double* denom  = colacc + 512;                // [64]
    double* invd   = denom + 64;                  // [64]

    const int t  = threadIdx.x;
    const int tx = t & 15, ty = t >> 4;
    const int bh = blockIdx.x;
    const int b  = bh >> 4, h = bh & 15;

    colacc[t]       = 0.0;
    colacc[t + 256] = 0.0;

    const size_t base = ((size_t)b * TS) * TE + (size_t)h * TD;

    // Q-tile prefetch lanes: r = row within tile, qb picks 16-col group
    const int r  = t & 63;
    const int qb = t >> 6;           // 0..3
    // K-tile prefetch lanes: s = row within 128-tile, hv picks 32-col half
    const int s_ld = t & 127;
    const int hv   = t >> 7;         // 0..1

    float4 qreg[4];
    float4 kreg[8];

    // prefetch Q tile qt=0
    {
        const float* qrow = g_Q + base + (size_t)r * TE + qb * 16;
#pragma unroll
        for (int c = 0; c < 4; c++)
            qreg[c] = *(const float4*)(qrow + c * 4);
    }

    for (int qt = 0; qt < 8; qt++) {
        __syncthreads();   // previous colacc (Es reads) done before overwrites
        {
#pragma unroll
            for (int c = 0; c < 4; c++) {
                int q = qb * 4 + c;
                Qs[(q*4+0)*64 + r] = qreg[c].x;
                Qs[(q*4+1)*64 + r] = qreg[c].y;
                Qs[(q*4+2)*64 + r] = qreg[c].z;
                Qs[(q*4+3)*64 + r] = qreg[c].w;
            }
        }
        if (t < 64) denom[t] = 0.0;

        // prefetch K tile kt=0
        {
            const float* krow = g_K + base + (size_t)s_ld * TE + hv * 32;
#pragma unroll
            for (int c = 0; c < 8; c++)
                kreg[c] = *(const float4*)(krow + c * 4);
        }
        __syncthreads();

        for (int kt = 0; kt < 4; kt++) {
            {
#pragma unroll
                for (int c = 0; c < 8; c++) {
                    int q = hv * 8 + c;
                    Ks[(q*4+0)*128 + s_ld] = kreg[c].x;
                    Ks[(q*4+1)*128 + s_ld] = kreg[c].y;
                    Ks[(q*4+2)*128 + s_ld] = kreg[c].z;
                    Ks[(q*4+3)*128 + s_ld] = kreg[c].w;
                }
            }
            __syncthreads();

            // prefetch next K tile (or next Q tile during last kt)
            if (kt < 3) {
                const float* krow = g_K + base + (size_t)((kt+1)*128 + s_ld) * TE + hv * 32;
#pragma unroll
                for (int c = 0; c < 8; c++)
                    kreg[c] = *(const float4*)(krow + c * 4);
            } else if (qt < 7) {
                const float* qrow = g_Q + base + (size_t)((qt+1)*64 + r) * TE + qb * 16;
#pragma unroll
                for (int c = 0; c < 4; c++)
                    qreg[c] = *(const float4*)(qrow + c * 4);
            }

            float acc[4][8];
#pragma unroll
            for (int i = 0; i < 4; i++)
#pragma unroll
                for (int j = 0; j < 8; j++) acc[i][j] = 0.f;

#pragma unroll 8
            for (int k = 0; k < 64; k++) {
                float4 av = *(const float4*)&Qs[k*64 + ty*4];
                float4 b0 = *(const float4*)&Ks[k*128 + tx*8];
                float4 b1 = *(const float4*)&Ks[k*128 + tx*8 + 4];
                float a[4]  = {av.x, av.y, av.z, av.w};
                float bb[8] = {b0.x, b0.y, b0.z, b0.w, b1.x, b1.y, b1.z, b1.w};
#pragma unroll
                for (int j = 0; j < 8; j++) {
                    acc[0][j] = fmaf(a[0], bb[j], acc[0][j]);
                    acc[1][j] = fmaf(a[1], bb[j], acc[1][j]);
                    acc[2][j] = fmaf(a[2], bb[j], acc[2][j]);
                    acc[3][j] = fmaf(a[3], bb[j], acc[3][j]);
                }
            }

#pragma unroll
            for (int i = 0; i < 4; i++) {
                float  e[8];
                double rs = 0.0;
#pragma unroll
                for (int j = 0; j < 8; j++) {
                    float sc = acc[i][j] * 0.125f + 1.0f;
                    e[j] = expf(sc);
                    rs += (double)e[j];
                }
                int row = ty * 4 + i;
                *(float4*)&Es[row*512 + kt*128 + tx*8]     = make_float4(e[0], e[1], e[2], e[3]);
                *(float4*)&Es[row*512 + kt*128 + tx*8 + 4] = make_float4(e[4], e[5], e[6], e[7]);
                atomicAdd(&denom[row], rs);
            }
            __syncthreads();
        }

        if (t < 64) invd[t] = 1.0 / denom[t];
        __syncthreads();

#pragma unroll
        for (int ss = 0; ss < 2; ss++) {
            int s = t + ss * 256;
            double a = colacc[s];
#pragma unroll 8
            for (int rr = 0; rr < 64; rr++)
                a = fma((double)Es[rr*512 + s], invd[rr], a);
            colacc[s] = a;
        }
    }

    g_colpart[(size_t)bh * TS + t]       = colacc[t];
    g_colpart[(size_t)bh * TS + t + 256] = colacc[t + 256];
}

// ---------------------------------------------------------------------------
// col -> log_softmax logits (fp64, deterministic tree reductions)
// ---------------------------------------------------------------------------
__global__ __launch_bounds__(512) void logits_kernel()
{
    __shared__ double red[512];
    const int b = blockIdx.x;
    const int s = threadIdx.x;

    double v = 0.0;
#pragma unroll
    for (int h = 0; h < TH; h++)
        v += g_colpart[((size_t)b * TH + h) * TS + s];

    red[s] = v;
    __syncthreads();
    for (int off = 256; off > 0; off >>= 1) {
        if (s < off) { double o = red[s + off]; if (o > red[s]) red[s] = o; }
        __syncthreads();
    }
    double m = red[0];
    __syncthreads();
    red[s] = exp(v - m);
    __syncthreads();
    for (int off = 256; off > 0; off >>= 1) {
        if (s < off) red[s] += red[s + off];
        __syncthreads();
    }
    double lse = m + log(red[0]);
    g_logits[(size_t)b * TS + s] = v - lse;
}

// ---------------------------------------------------------------------------
// Threefry-2x32 (JAX-exact, PARTITIONABLE mode: default since jax 0.4.36)
//   counter = 64-bit flat index via iota_2x32_shape: x0 = hi32 = 0, x1 = lo32 = i
//   32-bit draw = bits1 ^ bits2
// Then Gumbel-argmax categorical + gather.
// ---------------------------------------------------------------------------
__device__ __forceinline__ void threefry2x32(
    unsigned k0, unsigned k1, unsigned x0, unsigned x1,
    unsigned& o0, unsigned& o1)
{
    const unsigned ks0 = k0, ks1 = k1, ks2 = k0 ^ k1 ^ 0x1BD11BDAu;
    x0 += ks0; x1 += ks1;
#define TF_RND(r) { x0 += x1; x1 = __funnelshift_l(x1, x1, r); x1 ^= x0; }
    TF_RND(13) TF_RND(15) TF_RND(26) TF_RND(6)   x0 += ks1; x1 += ks2 + 1u;
    TF_RND(17) TF_RND(29) TF_RND(16) TF_RND(24)  x0 += ks2; x1 += ks0 + 2u;
    TF_RND(13) TF_RND(15) TF_RND(26) TF_RND(6)   x0 += ks0; x1 += ks1 + 3u;
    TF_RND(17) TF_RND(29) TF_RND(16) TF_RND(24)  x0 += ks1; x1 += ks2 + 4u;
    TF_RND(13) TF_RND(15) TF_RND(26) TF_RND(6)   x0 += ks2; x1 += ks0 + 5u;
#undef TF_RND
    o0 = x0; o1 = x1;
}

__global__ __launch_bounds__(256) void sample_kernel(
    const float* __restrict__ tokens, float* __restrict__ out)
{
    const int warp = blockIdx.x * 8 + (threadIdx.x >> 5);   // 0..16383 = b*1024+j
    const int lane = threadIdx.x & 31;
    const int b = warp >> 10;
    const int j = warp & 1023;

    const double* lg = g_logits + (size_t)b * TS;

    double best = -1.0e300;
    int    bi   = 0;

    for (int s = lane; s < TS; s += 32) {
        unsigned i = (unsigned)warp * 512u + (unsigned)s;  // flat counter (< 2^23)
        unsigned o0, o1;
        threefry2x32(0u, 42u, 0u, i, o0, o1);              // (hi32=0, lo32=i)
        unsigned bits = o0 ^ o1;                           // partitionable 32-bit draw
        float f = __uint_as_float((bits >> 9) | 0x3f800000u) - 1.0f;
        float u = fmaxf(f, 1.17549435e-38f);          // jnp.finfo(f32).tiny
        double g = -log(-log((double)u));
        double v = g + lg[s];
        if (v > best) { best = v; bi = s; }           // first occurrence per lane
    }

#pragma unroll
    for (int off = 16; off > 0; off >>= 1) {
        double ov = __shfl_down_sync(0xffffffffu, best, off);
        int    oi = __shfl_down_sync(0xffffffffu, bi,   off);
        if (ov > best || (ov == best && oi < bi)) { best = ov; bi = oi; }
    }

    if (lane == 0)
        out[warp] = tokens[((size_t)b * TS + (size_t)bi) * TE + (size_t)j];
}

// ---------------------------------------------------------------------------
extern "C" void kernel_launch(void* const* d_in, const int* in_sizes, int n_in,
                              void* d_out, int out_size)
{
    (void)in_sizes; (void)n_in; (void)out_size;
    const float* tokens = (const float*)d_in[0];
    const float* Wq     = (const float*)d_in[1];
    const float* bq     = (const float*)d_in[2];
    const float* Wk     = (const float*)d_in[3];
    const float* bk     = (const float*)d_in[4];
    float* out = (float*)d_out;

    cudaFuncSetAttribute(attn_col_kernel,
                         cudaFuncAttributeMaxDynamicSharedMemorySize, ATTN_SMEM);

    gemm_qk_kernel<<<dim3(8, 64, 2), 256>>>(tokens, Wq, bq, Wk, bk);
    attn_col_kernel<<<256, 256, ATTN_SMEM>>>();
    logits_kernel<<<16, 512>>>();
    sample_kernel<<<2048, 256>>>(tokens, out);
}

// round 5
// speedup vs baseline: 1.1007x; 1.0755x over previous
#include <cuda_runtime.h>
#include <math.h>
#include <stdint.h>

#define TB 16
#define TS 512
#define TE 1024
#define TH 16
#define TD 64

// Scratch (device globals: allocation-free rule)
static __device__ float  g_Q[(size_t)TB * TS * TE];
static __device__ float  g_K[(size_t)TB * TS * TE];
static __device__ double g_colpart[TB * TH * TS];
static __device__ double g_logits[TB * TS];

// ---------------------------------------------------------------------------
// GEMM: C[8192,1024] = tokens[8192,1024] * W[1024,1024]^T + bias
// 128x128 tile, KC=16, 256 thr, register-prefetch pipeline, 2 blocks/SM.
// ---------------------------------------------------------------------------
__global__ __launch_bounds__(256, 2) void gemm_qk_kernel(
    const float* __restrict__ tokens,
    const float* __restrict__ Wq, const float* __restrict__ bq,
    const float* __restrict__ Wk, const float* __restrict__ bk)
{
    const float* W    = (blockIdx.z == 0) ? Wq : Wk;
    const float* bias = (blockIdx.z == 0) ? bq : bk;
    float*       C    = (blockIdx.z == 0) ? g_Q : g_K;

    __shared__ float As[16 * 128];   // As[k][m]
    __shared__ float Bs[16 * 128];   // Bs[k][n]

    const int t  = threadIdx.x;
    const int tx = t & 15, ty = t >> 4;
    const int m0 = blockIdx.y * 128;
    const int n0 = blockIdx.x * 128;
    const int lrow  = t & 127;
    const int lhalf = t >> 7;        // which 8-column half of the 16-k slab

    float acc[8][8];
#pragma unroll
    for (int i = 0; i < 8; i++)
#pragma unroll
        for (int j = 0; j < 8; j++) acc[i][j] = 0.f;

    const float* Arow = tokens + (size_t)(m0 + lrow) * TE + lhalf * 8;
    const float* Wrow = W      + (size_t)(n0 + lrow) * TE + lhalf * 8;

    // prefetch registers (next-stage global tile)
    float4 pa0, pa1, pb0, pb1;
    pa0 = *(const float4*)(Arow + 0);
    pa1 = *(const float4*)(Arow + 4);
    pb0 = *(const float4*)(Wrow + 0);
    pb1 = *(const float4*)(Wrow + 4);

    for (int kk = 0; kk < TE; kk += 16) {
        // scatter prefetched tile into transposed smem
        {
            int q0 = lhalf * 8;
            As[(q0+0)*128 + lrow] = pa0.x;
            As[(q0+1)*128 + lrow] = pa0.y;
            As[(q0+2)*128 + lrow] = pa0.z;
            As[(q0+3)*128 + lrow] = pa0.w;
            As[(q0+4)*128 + lrow] = pa1.x;
            As[(q0+5)*128 + lrow] = pa1.y;
            As[(q0+6)*128 + lrow] = pa1.z;
            As[(q0+7)*128 + lrow] = pa1.w;
            Bs[(q0+0)*128 + lrow] = pb0.x;
            Bs[(q0+1)*128 + lrow] = pb0.y;
            Bs[(q0+2)*128 + lrow] = pb0.z;
            Bs[(q0+3)*128 + lrow] = pb0.w;
            Bs[(q0+4)*128 + lrow] = pb1.x;
            Bs[(q0+5)*128 + lrow] = pb1.y;
            Bs[(q0+6)*128 + lrow] = pb1.z;
            Bs[(q0+7)*128 + lrow] = pb1.w;
        }
        __syncthreads();

        // issue next-stage LDG early; consumed only after next sync
        if (kk + 16 < TE) {
            pa0 = *(const float4*)(Arow + kk + 16);
            pa1 = *(const float4*)(Arow + kk + 20);
            pb0 = *(const float4*)(Wrow + kk + 16);
            pb1 = *(const float4*)(Wrow + kk + 20);
        }

#pragma unroll
        for (int k = 0; k < 16; k++) {
            float4 a0 = *(const float4*)&As[k*128 + ty*8];
            float4 a1 = *(const float4*)&As[k*128 + ty*8 + 4];
            float4 b0 = *(const float4*)&Bs[k*128 + tx*8];
            float4 b1 = *(const float4*)&Bs[k*128 + tx*8 + 4];
            float a[8]  = {a0.x, a0.y, a0.z, a0.w, a1.x, a1.y, a1.z, a1.w};
            float bb[8] = {b0.x, b0.y, b0.z, b0.w, b1.x, b1.y, b1.z, b1.w};
#pragma unroll
            for (int i = 0; i < 8; i++)
#pragma unroll
                for (int j = 0; j < 8; j++)
                    acc[i][j] = fmaf(a[i], bb[j], acc[i][j]);
        }
        __syncthreads();
    }

#pragma unroll
    for (int i = 0; i < 8; i++) {
        int m = m0 + ty * 8 + i;
#pragma unroll
        for (int j = 0; j < 8; j += 4) {
            int n = n0 + tx * 8 + j;
            float4 o;
            o.x = acc[i][j+0] + bias[n+0];
            o.y = acc[i][j+1] + bias[n+1];
            o.z = acc[i][j+2] + bias[n+2];
            o.w = acc[i][j+3] + bias[n+3];
            *(float4*)(C + (size_t)m * TE + n) = o;
        }
    }
}

// ---------------------------------------------------------------------------
// Fused attention-column kernel: one block per (b,h).
// Denominators: half-warp shfl_xor fp64 reduction + single-writer smem add
// (NO smem f64 atomics — those compile to ATOMS.CAS retry loops and were the
//  dominant cost). Each half-warp (tx lanes 0-15) exclusively owns rows
//  ty*4..ty*4+3, so lane tx==0 is the sole writer of those denom entries.
// ---------------------------------------------------------------------------
#define ATTN_SMEM ((64*512 + 64*64 + 64*128) * 4 + (512 + 64 + 64) * 8)

__global__ __launch_bounds__(256) void attn_col_kernel()
{
    extern __shared__ char smem_raw[];
    float*  Es     = (float*)smem_raw;            // [64][512] exp(scores)
    float*  Qs     = Es + 64 * 512;               // [64k][64r]
    float*  Ks     = Qs + 64 * 64;                // [64k][128s]
    double* colacc = (double*)(Ks + 64 * 128);    // [512]
    double* denom  = colacc + 512;                // [64]
    double* invd   = denom + 64;                  // [64]

    const int t  = threadIdx.x;
    const int tx = t & 15, ty = t >> 4;
    const int bh = blockIdx.x;
    const int b  = bh >> 4, h = bh & 15;

    colacc[t]       = 0.0;
    colacc[t + 256] = 0.0;

    const size_t base = ((size_t)b * TS) * TE + (size_t)h * TD;

    // Q-tile prefetch lanes: r = row within tile, qb picks 16-col group
    const int r  = t & 63;
    const int qb = t >> 6;           // 0..3
    // K-tile prefetch lanes: s = row within 128-tile, hv picks 32-col half
    const int s_ld = t & 127;
    const int hv   = t >> 7;         // 0..1

    float4 qreg[4];
    float4 kreg[8];

    // prefetch Q tile qt=0
    {
        const float* qrow = g_Q + base + (size_t)r * TE + qb * 16;
#pragma unroll
        for (int c = 0; c < 4; c++)
            qreg[c] = *(const float4*)(qrow + c * 4);
    }

    for (int qt = 0; qt < 8; qt++) {
        __syncthreads();   // previous colacc (Es reads) done before overwrites
        {
#pragma unroll
            for (int c = 0; c < 4; c++) {
                int q = qb * 4 + c;
                Qs[(q*4+0)*64 + r] = qreg[c].x;
                Qs[(q*4+1)*64 + r] = qreg[c].y;
                Qs[(q*4+2)*64 + r] = qreg[c].z;
                Qs[(q*4+3)*64 + r] = qreg[c].w;
            }
        }
        if (t < 64) denom[t] = 0.0;

        // prefetch K tile kt=0
        {
            const float* krow = g_K + base + (size_t)s_ld * TE + hv * 32;
#pragma unroll
            for (int c = 0; c < 8; c++)
                kreg[c] = *(const float4*)(krow + c * 4);
        }
        __syncthreads();

        for (int kt = 0; kt < 4; kt++) {
            {
#pragma unroll
                for (int c = 0; c < 8; c++) {
                    int q = hv * 8 + c;
                    Ks[(q*4+0)*128 + s_ld] = kreg[c].x;
                    Ks[(q*4+1)*128 + s_ld] = kreg[c].y;
                    Ks[(q*4+2)*128 + s_ld] = kreg[c].z;
                    Ks[(q*4+3)*128 + s_ld] = kreg[c].w;
                }
            }
            __syncthreads();

            // prefetch next K tile (or next Q tile during last kt)
            if (kt < 3) {
                const float* krow = g_K + base + (size_t)((kt+1)*128 + s_ld) * TE + hv * 32;
#pragma unroll
                for (int c = 0; c < 8; c++)
                    kreg[c] = *(const float4*)(krow + c * 4);
            } else if (qt < 7) {
                const float* qrow = g_Q + base + (size_t)((qt+1)*64 + r) * TE + qb * 16;
#pragma unroll
                for (int c = 0; c < 4; c++)
                    qreg[c] = *(const float4*)(qrow + c * 4);
            }

            float acc[4][8];
#pragma unroll
            for (int i = 0; i < 4; i++)
#pragma unroll
                for (int j = 0; j < 8; j++) acc[i][j] = 0.f;

#pragma unroll 8
            for (int k = 0; k < 64; k++) {
                float4 av = *(const float4*)&Qs[k*64 + ty*4];
                float4 b0 = *(const float4*)&Ks[k*128 + tx*8];
                float4 b1 = *(const float4*)&Ks[k*128 + tx*8 + 4];
                float a[4]  = {av.x, av.y, av.z, av.w};
                float bb[8] = {b0.x, b0.y, b0.z, b0.w, b1.x, b1.y, b1.z, b1.w};
#pragma unroll
                for (int j = 0; j < 8; j++) {
                    acc[0][j] = fmaf(a[0], bb[j], acc[0][j]);
                    acc[1][j] = fmaf(a[1], bb[j], acc[1][j]);
                    acc[2][j] = fmaf(a[2], bb[j], acc[2][j]);
                    acc[3][j] = fmaf(a[3], bb[j], acc[3][j]);
                }
            }

#pragma unroll
            for (int i = 0; i < 4; i++) {
                float  e[8];
                double rs = 0.0;
#pragma unroll
                for (int j = 0; j < 8; j++) {
                    float sc = acc[i][j] * 0.125f + 1.0f;
                    e[j] = expf(sc);
                    rs += (double)e[j];
                }
                int row = ty * 4 + i;
                *(float4*)&Es[row*512 + kt*128 + tx*8]     = make_float4(e[0], e[1], e[2], e[3]);
                *(float4*)&Es[row*512 + kt*128 + tx*8 + 4] = make_float4(e[4], e[5], e[6], e[7]);
                // half-warp (16 tx lanes) fp64 reduction, then sole-writer add
                rs += __shfl_xor_sync(0xffffffffu, rs, 8);
                rs += __shfl_xor_sync(0xffffffffu, rs, 4);
                rs += __shfl_xor_sync(0xffffffffu, rs, 2);
                rs += __shfl_xor_sync(0xffffffffu, rs, 1);
                if (tx == 0) denom[row] += rs;
            }
            __syncthreads();
        }

        if (t < 64) invd[t] = 1.0 / denom[t];
        __syncthreads();

#pragma unroll
        for (int ss = 0; ss < 2; ss++) {
            int s = t + ss * 256;
            double a = colacc[s];
#pragma unroll 8
            for (int rr = 0; rr < 64; rr++)
                a = fma((double)Es[rr*512 + s], invd[rr], a);
            colacc[s] = a;
        }
    }

    g_colpart[(size_t)bh * TS + t]       = colacc[t];
    g_colpart[(size_t)bh * TS + t + 256] = colacc[t + 256];
}

// ---------------------------------------------------------------------------
// col -> log_softmax logits (fp64, deterministic tree reductions)
// ---------------------------------------------------------------------------
__global__ __launch_bounds__(512) void logits_kernel()
{
    __shared__ double red[512];
    const int b = blockIdx.x;
    const int s = threadIdx.x;

    double v = 0.0;
#pragma unroll
    for (int h = 0; h < TH; h++)
        v += g_colpart[((size_t)b * TH + h) * TS + s];

    red[s] = v;
    __syncthreads();
    for (int off = 256; off > 0; off >>= 1) {
        if (s < off) { double o = red[s + off]; if (o > red[s]) red[s] = o; }
        __syncthreads();
    }
    double m = red[0];
    __syncthreads();
    red[s] = exp(v - m);
    __syncthreads();
    for (int off = 256; off > 0; off >>= 1) {
        if (s < off) red[s] += red[s + off];
        __syncthreads();
    }
    double lse = m + log(red[0]);
    g_logits[(size_t)b * TS + s] = v - lse;
}

// ---------------------------------------------------------------------------
// Threefry-2x32 (JAX-exact, PARTITIONABLE mode: default since jax 0.4.36)
//   counter = 64-bit flat index via iota_2x32_shape: x0 = hi32 = 0, x1 = lo32 = i
//   32-bit draw = bits1 ^ bits2
// Then Gumbel-argmax categorical + gather.
// ---------------------------------------------------------------------------
__device__ __forceinline__ void threefry2x32(
    unsigned k0, unsigned k1, unsigned x0, unsigned x1,
    unsigned& o0, unsigned& o1)
{
    const unsigned ks0 = k0, ks1 = k1, ks2 = k0 ^ k1 ^ 0x1BD11BDAu;
    x0 += ks0; x1 += ks1;
#define TF_RND(r) { x0 += x1; x1 = __funnelshift_l(x1, x1, r); x1 ^= x0; }
    TF_RND(13) TF_RND(15) TF_RND(26) TF_RND(6)   x0 += ks1; x1 += ks2 + 1u;
    TF_RND(17) TF_RND(29) TF_RND(16) TF_RND(24)  x0 += ks2; x1 += ks0 + 2u;
    TF_RND(13) TF_RND(15) TF_RND(26) TF_RND(6)   x0 += ks0; x1 += ks1 + 3u;
    TF_RND(17) TF_RND(29) TF_RND(16) TF_RND(24)  x0 += ks1; x1 += ks2 + 4u;
    TF_RND(13) TF_RND(15) TF_RND(26) TF_RND(6)   x0 += ks2; x1 += ks0 + 5u;
#undef TF_RND
    o0 = x0; o1 = x1;
}

__global__ __launch_bounds__(256) void sample_kernel(
    const float* __restrict__ tokens, float* __restrict__ out)
{
    const int warp = blockIdx.x * 8 + (threadIdx.x >> 5);   // 0..16383 = b*1024+j
    const int lane = threadIdx.x & 31;
    const int b = warp >> 10;
    const int j = warp & 1023;

    const double* lg = g_logits + (size_t)b * TS;

    double best = -1.0e300;
    int    bi   = 0;

    for (int s = lane; s < TS; s += 32) {
        unsigned i = (unsigned)warp * 512u + (unsigned)s;  // flat counter (< 2^23)
        unsigned o0, o1;
        threefry2x32(0u, 42u, 0u, i, o0, o1);              // (hi32=0, lo32=i)
        unsigned bits = o0 ^ o1;                           // partitionable 32-bit draw
        float f = __uint_as_float((bits >> 9) | 0x3f800000u) - 1.0f;
        float u = fmaxf(f, 1.17549435e-38f);          // jnp.finfo(f32).tiny
        double g = -log(-log((double)u));
        double v = g + lg[s];
        if (v > best) { best = v; bi = s; }           // first occurrence per lane
    }

#pragma unroll
    for (int off = 16; off > 0; off >>= 1) {
        double ov = __shfl_down_sync(0xffffffffu, best, off);
        int    oi = __shfl_down_sync(0xffffffffu, bi,   off);
        if (ov > best || (ov == best && oi < bi)) { best = ov; bi = oi; }
    }

    if (lane == 0)
        out[warp] = tokens[((size_t)b * TS + (size_t)bi) * TE + (size_t)j];
}

// ---------------------------------------------------------------------------
extern "C" void kernel_launch(void* const* d_in, const int* in_sizes, int n_in,
                              void* d_out, int out_size)
{
    (void)in_sizes; (void)n_in; (void)out_size;
    const float* tokens = (const float*)d_in[0];
    const float* Wq     = (const float*)d_in[1];
    const float* bq     = (const float*)d_in[2];
    const float* Wk     = (const float*)d_in[3];
    const float* bk     = (const float*)d_in[4];
    float* out = (float*)d_out;

    cudaFuncSetAttribute(attn_col_kernel,
                         cudaFuncAttributeMaxDynamicSharedMemorySize, ATTN_SMEM);

    gemm_qk_kernel<<<dim3(8, 64, 2), 256>>>(tokens, Wq, bq, Wk, bk);
    attn_col_kernel<<<256, 256, ATTN_SMEM>>>();
    logits_kernel<<<16, 512>>>();
    sample_kernel<<<2048, 256>>>(tokens, out);
}

// round 7
// speedup vs baseline: 1.1377x; 1.0336x over previous
#include <cuda_runtime.h>
#include <cuda_bf16.h>
#include <math.h>
#include <stdint.h>

#define TB 16
#define TS 512
#define TE 1024
#define TH 16
#define TD 64
#define KSPLIT 3072          // 3 * TE (bf16 hi|mid|lo splits along K)

// Scratch (device globals: allocation-free rule)
static __device__ float  g_Q[(size_t)TB * TS * TE];
static __device__ float  g_K[(size_t)TB * TS * TE];
static __device__ double g_colpart[TB * TH * TS];
static __device__ double g_logits[TB * TS];
static __device__ __align__(128) __nv_bfloat16 g_As[(size_t)TB * TS * KSPLIT]; // tokens split
static __device__ __align__(128) __nv_bfloat16 g_Ws[(size_t)2 * TE * KSPLIT];  // Wq/Wk split

// ---------------------------------------------------------------------------
// PTX helpers (sm_80-class only: mma.sync / ldmatrix / cp.async — NO tcgen05,
// the harness PTX target is plain sm_103 which rejects 'a'-suffix features)
// ---------------------------------------------------------------------------
__device__ __forceinline__ uint32_t smem_u32(const void* p) {
    uint32_t a;
    asm("{ .reg .u64 t; cvta.to.shared.u64 t, %1; cvt.u32.u64 %0, t; }" : "=r"(a) : "l"(p));
    return a;
}
#define SW128(o) ((o) ^ ((((uint32_t)(o)) >> 3) & 0x70u))

#define CP_ASYNC16(dst, src) \
    asm volatile("cp.async.cg.shared.global [%0], [%1], 16;" :: "r"(dst), "l"(src))
#define CP_COMMIT()  asm volatile("cp.async.commit_group;" ::: "memory")
#define CP_WAIT1()   asm volatile("cp.async.wait_group 1;" ::: "memory")
#define CP_WAIT0()   asm volatile("cp.async.wait_group 0;" ::: "memory")

#define LDSM_X4(r0, r1, r2, r3, a) \
    asm volatile("ldmatrix.sync.aligned.m8n8.x4.shared.b16 {%0,%1,%2,%3}, [%4];" \
                 : "=r"(r0), "=r"(r1), "=r"(r2), "=r"(r3) : "r"(a))

#define MMA_16816(D, A, B0, B1) \
    asm volatile("mma.sync.aligned.m16n8k16.row.col.f32.bf16.bf16.f32 " \
                 "{%0,%1,%2,%3}, {%4,%5,%6,%7}, {%8,%9}, {%0,%1,%2,%3};" \
                 : "+f"((D)[0]), "+f"((D)[1]), "+f"((D)[2]), "+f"((D)[3]) \
                 : "r"((A)[0]), "r"((A)[1]), "r"((A)[2]), "r"((A)[3]), \
                   "r"(B0), "r"(B1))

// ---------------------------------------------------------------------------
// Exact 3-way bf16 split: x == hi + mid + lo (residuals exactly representable)
// ---------------------------------------------------------------------------
__device__ __forceinline__ void split3(float x, unsigned short& h, unsigned short& m,
                                       unsigned short& l) {
    __nv_bfloat16 bh = __float2bfloat16_rn(x);
    float r  = x - __bfloat162float(bh);
    __nv_bfloat16 bm = __float2bfloat16_rn(r);
    float r2 = r - __bfloat162float(bm);
    __nv_bfloat16 bl = __float2bfloat16_rn(r2);
    h = __bfloat16_as_ushort(bh);
    m = __bfloat16_as_ushort(bm);
    l = __bfloat16_as_ushort(bl);
}

__device__ __forceinline__ void split_store4(const float4 v, __nv_bfloat16* dst) {
    unsigned short h[4], m[4], l[4];
    split3(v.x, h[0], m[0], l[0]);
    split3(v.y, h[1], m[1], l[1]);
    split3(v.z, h[2], m[2], l[2]);
    split3(v.w, h[3], m[3], l[3]);
    uint2 uh = make_uint2((uint32_t)h[0] | ((uint32_t)h[1] << 16),
                          (uint32_t)h[2] | ((uint32_t)h[3] << 16));
    uint2 um = make_uint2((uint32_t)m[0] | ((uint32_t)m[1] << 16),
                          (uint32_t)m[2] | ((uint32_t)m[3] << 16));
    uint2 ul = make_uint2((uint32_t)l[0] | ((uint32_t)l[1] << 16),
                          (uint32_t)l[2] | ((uint32_t)l[3] << 16));
    *(uint2*)(dst)            = uh;
    *(uint2*)(dst + TE)       = um;
    *(uint2*)(dst + 2 * TE)   = ul;
}

// tokens [8192,1024] fp32 -> g_As [8192, 3072] bf16 (hi|mid|lo thirds)
__global__ __launch_bounds__(256) void split_tokens_kernel(const float* __restrict__ x)
{
    size_t i = (size_t)blockIdx.x * 256 + threadIdx.x;     // float4 index
    float4 v = ((const float4*)x)[i];
    size_t row = i >> 8;
    int    c4  = (int)(i & 255) * 4;
    split_store4(v, g_As + row * KSPLIT + c4);
}

// Wq/Wk [1024,1024] fp32 -> g_Ws [2][1024, 3072] bf16
__global__ __launch_bounds__(256) void split_w_kernel(const float* __restrict__ Wq,
                                                      const float* __restrict__ Wk)
{
    const float* W = (blockIdx.z == 0) ? Wq : Wk;
    size_t i = (size_t)blockIdx.x * 256 + threadIdx.x;
    float4 v = ((const float4*)W)[i];
    size_t row = i >> 8;
    int    c4  = (int)(i & 255) * 4;
    split_store4(v, g_Ws + (size_t)blockIdx.z * TE * KSPLIT + row * KSPLIT + c4);
}

// ---------------------------------------------------------------------------
// HMMA GEMM: C[8192,1024] = sum over 6 (pa,pb) segment pairs of
//   A_pa[8192,1024]bf16 . B_pb[1024,1024]bf16^T   + bias
// 6-term split product: hh + mh + lh + hm + mm + hl (dropped ml/lm/ll ~2^-24).
// Tile 128x128; 8 warps (warp tile 32x64); K-chunk 64; cp.async 3-stage.
// segA = [0,1,2,0,1,0], segB = [0,0,0,1,1,2]  (0=hi, 1=mid, 2=lo)
// ---------------------------------------------------------------------------
#define GEMM_STAGES 3
#define GEMM_STAGE_BYTES 32768                 // A 16KB + B 16KB
#define GEMM_SMEM (GEMM_STAGES * GEMM_STAGE_BYTES)
#define NCHUNK 96                              // 6 segs * 16 chunks of k64

__global__ __launch_bounds__(256) void gemm_hmma_kernel(const float* __restrict__ bq,
                                                        const float* __restrict__ bk)
{
    extern __shared__ char dsm[];
    const uint32_t smem_base = smem_u32(dsm);

    const int t    = threadIdx.x;
    const int lane = t & 31, wid = t >> 5;
    const int warp_m = wid & 3;                // 4 warps over M
    const int warp_n = wid >> 2;               // 2 warps over N
    const int sel = blockIdx.z;
    const int m0  = blockIdx.y * 128;
    const int n0  = blockIdx.x * 128;

    float*       C    = sel ? g_K : g_Q;
    const float* bias = sel ? bk : bq;

    // ---- gmem->smem load assignment: 2 threads/row, 64B each (4 x 16B)
    const int row  = t >> 1;
    const int half = t & 1;
    const char* aG = (const char*)(g_As + (size_t)(m0 + row) * KSPLIT + half * 32);
    const char* bG = (const char*)(g_Ws + (size_t)sel * TE * KSPLIT
                                        + (size_t)(n0 + row) * KSPLIT + half * 32);
    uint32_t dOffA[4], dOffB[4];
#pragma unroll
    for (int i = 0; i < 4; i++) {
        uint32_t o = SW128((uint32_t)(row * 128 + half * 64 + i * 16));
        dOffA[i] = o;
        dOffB[i] = 16384u + o;
    }
    // packed segment tables: 4 bits per segment
    const uint32_t segA = 0x0010210u;   // [0,1,2,0,1,0]  (seg 0 in low nibble)
    const uint32_t segB = 0x0211000u;   // [0,0,0,1,1,2]

#define ISSUE_STAGE(c_) do {                                                   \
    int _c = (c_);                                                             \
    int _seg = _c >> 4, _kc = _c & 15;                                         \
    int _pa = (segA >> (_seg * 4)) & 7, _pb = (segB >> (_seg * 4)) & 7;        \
    uint32_t _sb = smem_base + (_c % GEMM_STAGES) * GEMM_STAGE_BYTES;          \
    const char* _as = aG + (_pa * 1024 + _kc * 64) * 2;                        \
    const char* _bs = bG + (_pb * 1024 + _kc * 64) * 2;                        \
    _Pragma("unroll")                                                          \
    for (int _i = 0; _i < 4; _i++) {                                           \
        CP_ASYNC16(_sb + dOffA[_i], _as + _i * 16);                            \
        CP_ASYNC16(_sb + dOffB[_i], _bs + _i * 16);                            \
    }                                                                          \
    CP_COMMIT();                                                               \
} while (0)

    float acc[2][8][4];
#pragma unroll
    for (int i = 0; i < 2; i++)
#pragma unroll
        for (int j = 0; j < 8; j++)
#pragma unroll
            for (int k = 0; k < 4; k++) acc[i][j][k] = 0.f;

    // ldmatrix per-thread addressing components
    const uint32_t lrow = lane & 15;           // row within 16-row group
    const uint32_t lcol = (lane >> 4) * 16;    // 0 or 16 bytes (k halves)

    ISSUE_STAGE(0);
    ISSUE_STAGE(1);

    for (int c = 0; c < NCHUNK; c++) {
        if (c < NCHUNK - 1) CP_WAIT1(); else CP_WAIT0();
        __syncthreads();
        if (c + 2 < NCHUNK) ISSUE_STAGE(c + 2);

        const uint32_t sb  = smem_base + (c % GEMM_STAGES) * GEMM_STAGE_BYTES;
        const uint32_t aRow = (uint32_t)(warp_m * 32) + lrow;
        const uint32_t bRow = (uint32_t)(warp_n * 64) + lrow;

#pragma unroll
        for (int kk = 0; kk < 4; kk++) {
            uint32_t a[2][4];
#pragma unroll
            for (int mt = 0; mt < 2; mt++) {
                uint32_t off = (aRow + mt * 16) * 128 + kk * 32 + lcol;
                LDSM_X4(a[mt][0], a[mt][1], a[mt][2], a[mt][3], sb + SW128(off));
            }
            uint32_t b[4][4];
#pragma unroll
            for (int nt2 = 0; nt2 < 4; nt2++) {
                uint32_t off = (bRow + nt2 * 16) * 128 + kk * 32 + lcol;
                LDSM_X4(b[nt2][0], b[nt2][1], b[nt2][2], b[nt2][3],
                        sb + 16384u + SW128(off));
            }
#pragma unroll
            for (int mt = 0; mt < 2; mt++)
#pragma unroll
                for (int nt2 = 0; nt2 < 4; nt2++) {
                    MMA_16816(acc[mt][nt2 * 2 + 0], a[mt], b[nt2][0], b[nt2][2]);
                    MMA_16816(acc[mt][nt2 * 2 + 1], a[mt], b[nt2][1], b[nt2][3]);
                }
        }
    }

    // ---- epilogue: fragment layout m16n8: rows t/4, t/4+8; cols 2*(t%4)
    const int er = lane >> 2;
    const int ec = (lane & 3) * 2;
#pragma unroll
    for (int mt = 0; mt < 2; mt++) {
        const int r0 = m0 + warp_m * 32 + mt * 16 + er;
#pragma unroll
        for (int nt = 0; nt < 8; nt++) {
            const int col = n0 + warp_n * 64 + nt * 8 + ec;
            const float bx = bias[col], by = bias[col + 1];
            float* p = C + (size_t)r0 * TE + col;
            *(float2*)p            = make_float2(acc[mt][nt][0] + bx, acc[mt][nt][1] + by);
            *(float2*)(p + 8 * TE) = make_float2(acc[mt][nt][2] + bx, acc[mt][nt][3] + by);
        }
    }
#undef ISSUE_STAGE
}

// ---------------------------------------------------------------------------
// Fused attention-column kernel (unchanged): one block per (b,h).
// ---------------------------------------------------------------------------
#define ATTN_SMEM ((64*512 + 64*64 + 64*128) * 4 + (512 + 64 + 64) * 8)

__global__ __launch_bounds__(256) void attn_col_kernel()
{
    extern __shared__ char smem_raw[];
    float*  Es     = (float*)smem_raw;            // [64][512] exp(scores)
    float*  Qs     = Es + 64 * 512;               // [64k][64r]
    float*  Ks     = Qs + 64 * 64;                // [64k][128s]
    double* colacc = (double*)(Ks + 64 * 128);    // [512]
    double* denom  = colacc + 512;                // [64]
    double* invd   = denom + 64;                  // [64]

    const int t  = threadIdx.x;
    const int tx = t & 15, ty = t >> 4;
    const int bh = blockIdx.x;
    const int b  = bh >> 4, h = bh & 15;

    colacc[t]       = 0.0;
    colacc[t + 256] = 0.0;

    const size_t base = ((size_t)b * TS) * TE + (size_t)h * TD;

    const int r  = t & 63;
    const int qb = t >> 6;
    const int s_ld = t & 127;
    const int hv   = t >> 7;

    float4 qreg[4];
    float4 kreg[8];

    {
        const float* qrow = g_Q + base + (size_t)r * TE + qb * 16;
#pragma unroll
        for (int c = 0; c < 4; c++)
            qreg[c] = *(const float4*)(qrow + c * 4);
    }

    for (int qt = 0; qt < 8; qt++) {
        __syncthreads();
        {
#pragma unroll
            for (int c = 0; c < 4; c++) {
                int q = qb * 4 + c;
                Qs[(q*4+0)*64 + r] = qreg[c].x;
                Qs[(q*4+1)*64 + r] = qreg[c].y;
                Qs[(q*4+2)*64 + r] = qreg[c].z;
                Qs[(q*4+3)*64 + r] = qreg[c].w;
            }
        }
        if (t < 64) denom[t] = 0.0;

        {
            const float* krow = g_K + base + (size_t)s_ld * TE + hv * 32;
#pragma unroll
            for (int c = 0; c < 8; c++)
                kreg[c] = *(const float4*)(krow + c * 4);
        }
        __syncthreads();

        for (int kt = 0; kt < 4; kt++) {
            {
#pragma unroll
                for (int c = 0; c < 8; c++) {
                    int q = hv * 8 + c;
                    Ks[(q*4+0)*128 + s_ld] = kreg[c].x;
                    Ks[(q*4+1)*128 + s_ld] = kreg[c].y;
                    Ks[(q*4+2)*128 + s_ld] = kreg[c].z;
                    Ks[(q*4+3)*128 + s_ld] = kreg[c].w;
                }
            }
            __syncthreads();

            if (kt < 3) {
                const float* krow = g_K + base + (size_t)((kt+1)*128 + s_ld) * TE + hv * 32;
#pragma unroll
                for (int c = 0; c < 8; c++)
                    kreg[c] = *(const float4*)(krow + c * 4);
            } else if (qt < 7) {
                const float* qrow = g_Q + base + (size_t)((qt+1)*64 + r) * TE + qb * 16;
#pragma unroll
                for (int c = 0; c < 4; c++)
                    qreg[c] = *(const float4*)(qrow + c * 4);
            }

            float acc[4][8];
#pragma unroll
            for (int i = 0; i < 4; i++)
#pragma unroll
                for (int j = 0; j < 8; j++) acc[i][j] = 0.f;

#pragma unroll 8
            for (int k = 0; k < 64; k++) {
                float4 av = *(const float4*)&Qs[k*64 + ty*4];
                float4 b0 = *(const float4*)&Ks[k*128 + tx*8];
                float4 b1 = *(const float4*)&Ks[k*128 + tx*8 + 4];
                float a[4]  = {av.x, av.y, av.z, av.w};
                float bb[8] = {b0.x, b0.y, b0.z, b0.w, b1.x, b1.y, b1.z, b1.w};
#pragma unroll
                for (int j = 0; j < 8; j++) {
                    acc[0][j] = fmaf(a[0], bb[j], acc[0][j]);
                    acc[1][j] = fmaf(a[1], bb[j], acc[1][j]);
                    acc[2][j] = fmaf(a[2], bb[j], acc[2][j]);
                    acc[3][j] = fmaf(a[3], bb[j], acc[3][j]);
                }
            }

#pragma unroll
            for (int i = 0; i < 4; i++) {
                float  e[8];
                double rs = 0.0;
#pragma unroll
                for (int j = 0; j < 8; j++) {
                    float sc = acc[i][j] * 0.125f + 1.0f;
                    e[j] = expf(sc);
                    rs += (double)e[j];
                }
                int rowi = ty * 4 + i;
                *(float4*)&Es[rowi*512 + kt*128 + tx*8]     = make_float4(e[0], e[1], e[2], e[3]);
                *(float4*)&Es[rowi*512 + kt*128 + tx*8 + 4] = make_float4(e[4], e[5], e[6], e[7]);
                rs += __shfl_xor_sync(0xffffffffu, rs, 8);
                rs += __shfl_xor_sync(0xffffffffu, rs, 4);
                rs += __shfl_xor_sync(0xffffffffu, rs, 2);
                rs += __shfl_xor_sync(0xffffffffu, rs, 1);
                if (tx == 0) denom[rowi] += rs;
            }
            __syncthreads();
        }

        if (t < 64) invd[t] = 1.0 / denom[t];
        __syncthreads();

#pragma unroll
        for (int ss = 0; ss < 2; ss++) {
            int s = t + ss * 256;
            double a = colacc[s];
#pragma unroll 8
            for (int rr = 0; rr < 64; rr++)
                a = fma((double)Es[rr*512 + s], invd[rr], a);
            colacc[s] = a;
        }
    }

    g_colpart[(size_t)bh * TS + t]       = colacc[t];
    g_colpart[(size_t)bh * TS + t + 256] = colacc[t + 256];
}

// ---------------------------------------------------------------------------
// col -> log_softmax logits (fp64, deterministic tree reductions)
// ---------------------------------------------------------------------------
__global__ __launch_bounds__(512) void logits_kernel()
{
    __shared__ double red[512];
    const int b = blockIdx.x;
    const int s = threadIdx.x;

    double v = 0.0;
#pragma unroll
    for (int h = 0; h < TH; h++)
        v += g_colpart[((size_t)b * TH + h) * TS + s];

    red[s] = v;
    __syncthreads();
    for (int off = 256; off > 0; off >>= 1) {
        if (s < off) { double o = red[s + off]; if (o > red[s]) red[s] = o; }
        __syncthreads();
    }
    double m = red[0];
    __syncthreads();
    red[s] = exp(v - m);
    __syncthreads();
    for (int off = 256; off > 0; off >>= 1) {
        if (s < off) red[s] += red[s + off];
        __syncthreads();
    }
    double lse = m + log(red[0]);
    g_logits[(size_t)b * TS + s] = v - lse;
}

// ---------------------------------------------------------------------------
// Threefry-2x32 (JAX-exact, PARTITIONABLE): bits = o0 ^ o1, counter (0, i)
// ---------------------------------------------------------------------------
__device__ __forceinline__ void threefry2x32(
    unsigned k0, unsigned k1, unsigned x0, unsigned x1,
    unsigned& o0, unsigned& o1)
{
    const unsigned ks0 = k0, ks1 = k1, ks2 = k0 ^ k1 ^ 0x1BD11BDAu;
    x0 += ks0; x1 += ks1;
#define TF_RND(r) { x0 += x1; x1 = __funnelshift_l(x1, x1, r); x1 ^= x0; }
    TF_RND(13) TF_RND(15) TF_RND(26) TF_RND(6)   x0 += ks1; x1 += ks2 + 1u;
    TF_RND(17) TF_RND(29) TF_RND(16) TF_RND(24)  x0 += ks2; x1 += ks0 + 2u;
    TF_RND(13) TF_RND(15) TF_RND(26) TF_RND(6)   x0 += ks0; x1 += ks1 + 3u;
    TF_RND(17) TF_RND(29) TF_RND(16) TF_RND(24)  x0 += ks1; x1 += ks2 + 4u;
    TF_RND(13) TF_RND(15) TF_RND(26) TF_RND(6)   x0 += ks2; x1 += ks0 + 5u;
#undef TF_RND
    o0 = x0; o1 = x1;
}

__global__ __launch_bounds__(256) void sample_kernel(
    const float* __restrict__ tokens, float* __restrict__ out)
{
    const int warp = blockIdx.x * 8 + (threadIdx.x >> 5);   // 0..16383 = b*1024+j
    const int lane = threadIdx.x & 31;
    const int b = warp >> 10;
    const int j = warp & 1023;

    const double* lg = g_logits + (size_t)b * TS;

    double best = -1.0e300;
    int    bi   = 0;

    for (int s = lane; s < TS; s += 32) {
        unsigned i = (unsigned)warp * 512u + (unsigned)s;
        unsigned o0, o1;
        threefry2x32(0u, 42u, 0u, i, o0, o1);
        unsigned bits = o0 ^ o1;
        float f = __uint_as_float((bits >> 9) | 0x3f800000u) - 1.0f;
        float u = fmaxf(f, 1.17549435e-38f);
        double g = -log(-log((double)u));
        double v = g + lg[s];
        if (v > best) { best = v; bi = s; }
    }

#pragma unroll
    for (int off = 16; off > 0; off >>= 1) {
        double ov = __shfl_down_sync(0xffffffffu, best, off);
        int    oi = __shfl_down_sync(0xffffffffu, bi,   off);
        if (ov > best || (ov == best && oi < bi)) { best = ov; bi = oi; }
    }

    if (lane == 0)
        out[warp] = tokens[((size_t)b * TS + (size_t)bi) * TE + (size_t)j];
}

// ---------------------------------------------------------------------------
extern "C" void kernel_launch(void* const* d_in, const int* in_sizes, int n_in,
                              void* d_out, int out_size)
{
    (void)in_sizes; (void)n_in; (void)out_size;
    const float* tokens = (const float*)d_in[0];
    const float* Wq     = (const float*)d_in[1];
    const float* bq     = (const float*)d_in[2];
    const float* Wk     = (const float*)d_in[3];
    const float* bk     = (const float*)d_in[4];
    float* out = (float*)d_out;

    cudaFuncSetAttribute(gemm_hmma_kernel,
                         cudaFuncAttributeMaxDynamicSharedMemorySize, GEMM_SMEM);
    cudaFuncSetAttribute(attn_col_kernel,
                         cudaFuncAttributeMaxDynamicSharedMemorySize, ATTN_SMEM);

    split_tokens_kernel<<<8192, 256>>>(tokens);
    split_w_kernel<<<dim3(1024, 1, 2), 256>>>(Wq, Wk);
    gemm_hmma_kernel<<<dim3(8, 64, 2), 256, GEMM_SMEM>>>(bq, bk);
    attn_col_kernel<<<256, 256, ATTN_SMEM>>>();
    logits_kernel<<<16, 512>>>();
    sample_kernel<<<2048, 256>>>(tokens, out);
}